// round 14
// baseline (speedup 1.0000x reference)
#include <cuda_runtime.h>

#define NN 100000

// ---- scratch (static __device__ globals; no allocation) ----
__device__ int    g_deg[NN];       // atomic-only during hist; reset each run
__device__ float  g_dinv[NN];      // read-only after node_prep
__device__ float4 g_S[NN];         // init {sx.xyz, dinv}; scatter adds {sx,0}
__device__ float4 g_Q[NN];         // READ-ONLY during scatter: {sx.xyz, 0}
__device__ float  g_w[NN];         // atomic-only during scatter: layer-2 weights
__device__ float  g_sum16[16];     // layer-2 16-dim reduction

// ---------------------------------------------------------------------------
// degree histogram over dst; one int2 (2 edges) per thread
__global__ void k_hist(const int* __restrict__ dst, int E) {
    int i    = blockIdx.x * blockDim.x + threadIdx.x;
    int half = E >> 1;
    const int2* dst2 = (const int2*)dst;
    if (i < half) {
        int2 d = __ldg(&dst2[i]);
        atomicAdd(&g_deg[d.x], 1);
        atomicAdd(&g_deg[d.y], 1);
    }
    if (i == 0 && (E & 1)) atomicAdd(&g_deg[dst[E - 1]], 1);
    cudaTriggerProgrammaticLaunchCompletion();
}

// per-node prep; x-loads issued BEFORE the grid dependency sync (overlap hist tail)
__global__ void k_node_prep(const float* __restrict__ x) {
    int v = blockIdx.x * blockDim.x + threadIdx.x;
    float x0 = 0.f, x1 = 0.f, x2 = 0.f;
    if (v < NN) {                         // independent of hist
        x0 = __ldg(&x[3 * v + 0]);
        x1 = __ldg(&x[3 * v + 1]);
        x2 = __ldg(&x[3 * v + 2]);
    }
    cudaGridDependencySynchronize();      // hist atomics now visible
    if (blockIdx.x == 0 && threadIdx.x < 16) g_sum16[threadIdx.x] = 0.f;
    if (v < NN) {
        float d = rsqrtf((float)(g_deg[v] + 1));
        g_deg[v]  = 0;                    // deterministic across graph replays
        g_dinv[v] = d;
        g_w[v]    = d;                    // self-loop term of layer-2 weight
        float sx0 = d * x0, sx1 = d * x1, sx2 = d * x2;
        g_Q[v] = make_float4(sx0, sx1, sx2, 0.f);
        g_S[v] = make_float4(sx0, sx1, sx2, d);  // self-loop pre-included; w = dinv
    }
    cudaTriggerProgrammaticLaunchCompletion();
}

// fused edge pass, one int2 (2 edges) per thread, 4 random wf/edge;
// index loads issued BEFORE the sync (overlap node_prep tail)
__global__ void k_scatter(const int* __restrict__ src,
                          const int* __restrict__ dst, int E) {
    int i    = blockIdx.x * blockDim.x + threadIdx.x;
    int half = E >> 1;
    const int2* src2 = (const int2*)src;
    const int2* dst2 = (const int2*)dst;
    int2 s = make_int2(0, 0), d = make_int2(0, 0);
    bool act = (i < half);
    if (act) {                            // independent of node_prep
        s = __ldg(&src2[i]);
        d = __ldg(&dst2[i]);
    }
    cudaGridDependencySynchronize();      // Q/dinv/S/w now initialized
    if (act) {
        float4 q0 = __ldg(&g_Q[s.x]);
        float4 q1 = __ldg(&g_Q[s.y]);
        float dd0 = __ldg(&g_dinv[d.x]);
        float dd1 = __ldg(&g_dinv[d.y]);
        asm volatile("red.global.add.v4.f32 [%0], {%1,%2,%3,%4};"
                     :: "l"(&g_S[d.x]), "f"(q0.x), "f"(q0.y), "f"(q0.z), "f"(q0.w)
                     : "memory");
        asm volatile("red.global.add.f32 [%0], %1;"
                     :: "l"(&g_w[s.x]), "f"(dd0)
                     : "memory");
        asm volatile("red.global.add.v4.f32 [%0], {%1,%2,%3,%4};"
                     :: "l"(&g_S[d.y]), "f"(q1.x), "f"(q1.y), "f"(q1.z), "f"(q1.w)
                     : "memory");
        asm volatile("red.global.add.f32 [%0], %1;"
                     :: "l"(&g_w[s.y]), "f"(dd1)
                     : "memory");
    }
    if (i == 0 && (E & 1)) {
        int ss = src[E - 1], dd = dst[E - 1];
        float4 q = __ldg(&g_Q[ss]);
        float dv = __ldg(&g_dinv[dd]);
        asm volatile("red.global.add.v4.f32 [%0], {%1,%2,%3,%4};"
                     :: "l"(&g_S[dd]), "f"(q.x), "f"(q.y), "f"(q.z), "f"(q.w)
                     : "memory");
        asm volatile("red.global.add.f32 [%0], %1;"
                     :: "l"(&g_w[ss]), "f"(dv)
                     : "memory");
    }
    cudaTriggerProgrammaticLaunchCompletion();
}

// layer-1 per-node + layer-2 accumulation; 20B/node (S + w):
//   a = dinv*S.xyz;  h1 = relu(a @ W1 + b1);  sum16 += (w*dinv)*h1
__global__ void k_layer1(const float* __restrict__ W1, const float* __restrict__ b1) {
    int v = blockIdx.x * blockDim.x + threadIdx.x;
    cudaGridDependencySynchronize();      // scatter atomics now visible
    float acc[16];
    #pragma unroll
    for (int j = 0; j < 16; j++) acc[j] = 0.f;

    if (v < NN) {
        float4 S = g_S[v];                // {agg.xyz (incl. self), dinv}
        float  d = S.w;
        float  wv = g_w[v] * d;
        float a0 = d * S.x;
        float a1 = d * S.y;
        float a2 = d * S.z;
        #pragma unroll
        for (int j = 0; j < 16; j++) {
            float h = __ldg(&b1[j])
                    + a0 * __ldg(&W1[j])
                    + a1 * __ldg(&W1[16 + j])
                    + a2 * __ldg(&W1[32 + j]);
            acc[j] = wv * fmaxf(h, 0.f);
        }
    }

    #pragma unroll
    for (int j = 0; j < 16; j++) {
        #pragma unroll
        for (int o = 16; o > 0; o >>= 1)
            acc[j] += __shfl_down_sync(0xffffffffu, acc[j], o);
    }
    __shared__ float sm[8][16];
    int lane = threadIdx.x & 31, w = threadIdx.x >> 5;
    if (lane == 0) {
        #pragma unroll
        for (int j = 0; j < 16; j++) sm[w][j] = acc[j];
    }
    __syncthreads();
    if (threadIdx.x < 16) {
        float s = 0.f;
        #pragma unroll
        for (int ww = 0; ww < 8; ww++) s += sm[ww][threadIdx.x];
        atomicAdd(&g_sum16[threadIdx.x], s);
    }
    cudaTriggerProgrammaticLaunchCompletion();
}

// final: out[j] = (sum16/N) @ W2 + b2
__global__ void k_final(const float* __restrict__ W2, const float* __restrict__ b2,
                        float* __restrict__ out) {
    int j = threadIdx.x;
    float bj = (j < 32) ? __ldg(&b2[j]) : 0.f;   // independent prologue
    cudaGridDependencySynchronize();
    if (j >= 32) return;
    float s = bj;
    const float inv_n = 1.0f / (float)NN;
    #pragma unroll
    for (int k = 0; k < 16; k++)
        s += (g_sum16[k] * inv_n) * __ldg(&W2[k * 32 + j]);
    out[j] = s;
}

// ---------------------------------------------------------------------------
template <typename... Args>
static void launch_pdl(void (*kern)(Args...), dim3 grid, dim3 block, Args... args) {
    cudaLaunchConfig_t cfg = {};
    cfg.gridDim  = grid;
    cfg.blockDim = block;
    cudaLaunchAttribute attr[1];
    attr[0].id = cudaLaunchAttributeProgrammaticStreamSerialization;
    attr[0].val.programmaticStreamSerializationAllowed = 1;
    cfg.attrs    = attr;
    cfg.numAttrs = 1;
    cudaLaunchKernelEx(&cfg, kern, args...);
}

extern "C" void kernel_launch(void* const* d_in, const int* in_sizes, int n_in,
                              void* d_out, int out_size) {
    const float* x   = (const float*)d_in[0];
    const int*   ei  = (const int*)d_in[1];
    const float* W1  = (const float*)d_in[2];
    const float* b1  = (const float*)d_in[3];
    const float* W2  = (const float*)d_in[4];
    const float* b2  = (const float*)d_in[5];
    float*       out = (float*)d_out;

    int E = in_sizes[1] / 2;
    const int* src = ei;
    const int* dst = ei + E;

    int nb_nodes = (NN + 255) / 256;
    int nb_half  = ((E / 2) + 255) / 256;

    k_hist<<<nb_half, 256>>>(dst, E);
    launch_pdl(k_node_prep, dim3(nb_nodes), dim3(256), x);
    launch_pdl(k_scatter, dim3(nb_half), dim3(256), src, dst, E);
    launch_pdl(k_layer1, dim3(nb_nodes), dim3(256), W1, b1);
    launch_pdl(k_final, dim3(1), dim3(32), W2, b2, out);
}